// round 13
// baseline (speedup 1.0000x reference)
#include <cuda_runtime.h>
#include <cuda_fp16.h>
#include <cstdint>
#include <math.h>

#define NC      64
#define DHEAD   128
#define BATCHB  512
#define COLS    8192
#define NTILES  1024            // per gram: t = g*g + i, g in [0,32), i in [0,2g]
#define KC      64              // k-halfs per chunk (128B row)
#define NCH     8
#define ROWB    144             // smem row stride bytes (64 halfs + 8 pad)
#define M_ROWS  128
#define N_ROWS  256
#define A_ST    (M_ROWS * ROWB)              // 18432
#define STG     ((M_ROWS + N_ROWS) * ROWB)   // 55296 per stage
#define NSTG    3
#define SMEM_DYN (NSTG * STG)                // 165888 -> 1 CTA/SM

// fp16 of 256*q^2, transposed [gram][col][b]  (16.8 MB, L2-resident)
__device__ __half g_Xt[2ULL * COLS * BATCHB];
__device__ float  g_acc[4];

__device__ __forceinline__ float fsqrt_fast(float x) {
    float r; asm("sqrt.approx.f32 %0, %1;" : "=f"(r) : "f"(x)); return r;
}
__device__ __forceinline__ uint32_t smem_u32(const void* p) {
    uint32_t a;
    asm("{ .reg .u64 t; cvta.to.shared.u64 t, %1; cvt.u32.u64 %0, t; }" : "=r"(a) : "l"(p));
    return a;
}
#define CP16(dst, src) \
    asm volatile("cp.async.cg.shared.global [%0], [%1], 16;" :: "r"(dst), "l"(src))
#define CP_COMMIT() asm volatile("cp.async.commit_group;" ::: "memory")
#define CP_WAIT1()  asm volatile("cp.async.wait_group 1;"  ::: "memory")
#define CP_WAIT0()  asm volatile("cp.async.wait_group 0;"  ::: "memory")
#define LDSM_X4(r0, r1, r2, r3, a) \
    asm volatile("ldmatrix.sync.aligned.m8n8.x4.shared.b16 {%0,%1,%2,%3}, [%4];" \
                 : "=r"(r0), "=r"(r1), "=r"(r2), "=r"(r3) : "r"(a))
#define MMA(d, a0, a1, a2, a3, b0, b1) \
    asm volatile( \
        "mma.sync.aligned.m16n8k16.row.col.f32.f16.f16.f32 " \
        "{%0,%1,%2,%3}, {%4,%5,%6,%7}, {%8,%9}, {%0,%1,%2,%3};" \
        : "+f"((d)[0]), "+f"((d)[1]), "+f"((d)[2]), "+f"((d)[3]) \
        : "r"(a0), "r"(a1), "r"(a2), "r"(a3), "r"(b0), "r"(b1))

// ---------------- kernel 0 ----------------
__global__ void k_zero() { if (threadIdx.x < 4) g_acc[threadIdx.x] = 0.0f; }

// ---------------- kernel 1: softmax -> fp16 256*q^2 transposed + self-sim dot ----------------
__global__ void k_softmax(const float* __restrict__ emb) {
    const int c    = blockIdx.y;
    const int b0   = blockIdx.x * 16;
    const int w    = threadIdx.x >> 5;
    const int lane = threadIdx.x & 31;

    __shared__ __align__(16) __half sm_t[2][DHEAD][16];
    __shared__ float dotred[16];

    const int b = b0 + w;
    const float* pa = emb + (size_t)b * COLS + c * DHEAD;
    const float* pb = emb + (size_t)(b + BATCHB) * COLS + c * DHEAD;

    float xa[4], xb[4];
#pragma unroll
    for (int p = 0; p < 4; ++p) { xa[p] = pa[lane + 32 * p]; xb[p] = pb[lane + 32 * p]; }

    float ma = fmaxf(fmaxf(xa[0], xa[1]), fmaxf(xa[2], xa[3]));
    float mb = fmaxf(fmaxf(xb[0], xb[1]), fmaxf(xb[2], xb[3]));
#pragma unroll
    for (int off = 16; off > 0; off >>= 1) {
        ma = fmaxf(ma, __shfl_xor_sync(0xFFFFFFFFu, ma, off));
        mb = fmaxf(mb, __shfl_xor_sync(0xFFFFFFFFu, mb, off));
    }
    float ea[4], eb[4], sa = 0.f, sb = 0.f;
#pragma unroll
    for (int p = 0; p < 4; ++p) {
        ea[p] = __expf(xa[p] - ma); sa += ea[p];
        eb[p] = __expf(xb[p] - mb); sb += eb[p];
    }
#pragma unroll
    for (int off = 16; off > 0; off >>= 1) {
        sa += __shfl_xor_sync(0xFFFFFFFFu, sa, off);
        sb += __shfl_xor_sync(0xFFFFFFFFu, sb, off);
    }
    const float ia = 16.0f / sa, ib = 16.0f / sb;
    float dot = 0.f;
#pragma unroll
    for (int p = 0; p < 4; ++p) {
        float qa = ea[p] * ia;                       // 16*q_a
        float qb = eb[p] * ib;
        dot += qa * qb;                              // 256*qa*qb
        sm_t[0][lane + 32 * p][w] = __float2half_rn(qa * qa);   // 256*q^2
        sm_t[1][lane + 32 * p][w] = __float2half_rn(qb * qb);
    }
#pragma unroll
    for (int off = 16; off > 0; off >>= 1)
        dot += __shfl_xor_sync(0xFFFFFFFFu, dot, off);
    if (lane == 0) dotred[w] = dot;
    __syncthreads();
    if (threadIdx.x == 0) {
        float s = 0.f;
#pragma unroll
        for (int k = 0; k < 16; ++k) s += dotred[k];
        atomicAdd(&g_acc[0], s * (1.0f / 256.0f));
    }
    const int tid = threadIdx.x;
    const int g = tid >> 8;
    const int d = (tid >> 1) & 127;
    const int h = tid & 1;
    uint4 v = *(const uint4*)&sm_t[g][d][h * 8];
    __half* dst = g_Xt + (size_t)g * COLS * BATCHB
                + (size_t)(c * DHEAD + d) * BATCHB + (b0 + h * 8);
    *(uint4*)dst = v;
}

// ---------------- kernel 2: 128x256 Gram tile, warp tile 64x64, 1 CTA/SM ----------------
// grid (1024, 2): x = tile t = g*g + i; rows = cluster i (128), cols = clusters {2g,2g+1}.
// 8 warps: wm = wid&1 (2 x 64 rows), wn = wid>>1 (4 x 64 cols).
__global__ void __launch_bounds__(256, 1) k_gram() {
    extern __shared__ __align__(16) char dsm[];
    __shared__ float wsum[8];

    const uint32_t sbase = smem_u32(dsm);
    const int tid  = threadIdx.x;
    const int wid  = tid >> 5;
    const int lane = tid & 31;

    // tile decode: t = g*g + i
    const int t = blockIdx.x;
    int g = (int)sqrtf((float)t);
    while (g * g > t) --g;
    while ((g + 1) * (g + 1) <= t) ++g;
    const int i = t - g * g;                 // 0 .. 2g
    const bool skipL = (i == 2 * g);         // left 128 cols are the diagonal block
    const int gram = blockIdx.y;

    const __half* xg = g_Xt + (size_t)gram * COLS * BATCHB;
    const __half* gA = xg + (size_t)i * DHEAD * BATCHB;          // 128 rows (M)
    const __half* gB = xg + (size_t)(2 * g) * DHEAD * BATCHB;    // 256 rows (N)

    const int wr = (wid & 1) * 64;     // warp row base
    const int wc = (wid >> 1) * 64;    // warp col base

    const int lrow = lane & 15;
    const uint32_t lkb = (uint32_t)(lane >> 4) * 16;
    const uint32_t aoff_l = (uint32_t)(wr + lrow) * ROWB + lkb;
    const uint32_t boff_l = A_ST + (uint32_t)(wc + lrow) * ROWB + lkb;

    float acc[4][8][4];
#pragma unroll
    for (int a = 0; a < 4; ++a)
#pragma unroll
        for (int b = 0; b < 8; ++b)
#pragma unroll
            for (int c2 = 0; c2 < 4; ++c2) acc[a][b][c2] = 0.f;

    // loader: A 128 rows (4 CP16/thr) + B 256 rows (8 CP16/thr)
    auto load_chunk = [&](int st, int ch) {
        const uint32_t ao = sbase + st * STG;
        const uint32_t bo = ao + A_ST;
#pragma unroll
        for (int it = 0; it < 4; ++it) {
            const int u = tid + it * 256;             // 0..1023
            const int r = u >> 3, seg = u & 7;
            CP16(ao + r * ROWB + seg * 16, gA + (size_t)r * BATCHB + ch * KC + seg * 8);
        }
#pragma unroll
        for (int it = 0; it < 8; ++it) {
            const int u = tid + it * 256;             // 0..2047
            const int r = u >> 3, seg = u & 7;
            CP16(bo + r * ROWB + seg * 16, gB + (size_t)r * BATCHB + ch * KC + seg * 8);
        }
        CP_COMMIT();
    };

    load_chunk(0, 0);
    load_chunk(1, 1);

#pragma unroll 1
    for (int ch = 0; ch < NCH; ++ch) {
        if (ch + 1 < NCH) CP_WAIT1(); else CP_WAIT0();
        __syncthreads();

        const uint32_t sst = sbase + (ch % NSTG) * STG;
        const uint32_t pa = sst + aoff_l;
        const uint32_t pb = sst + boff_l;

#pragma unroll
        for (int ks = 0; ks < 4; ++ks) {
            const uint32_t kb = (uint32_t)ks * 32;
            uint32_t af[4][4], bf[4][4];
            LDSM_X4(af[0][0], af[0][1], af[0][2], af[0][3], pa + kb);
            LDSM_X4(af[1][0], af[1][1], af[1][2], af[1][3], pa + 16 * ROWB + kb);
            LDSM_X4(af[2][0], af[2][1], af[2][2], af[2][3], pa + 32 * ROWB + kb);
            LDSM_X4(af[3][0], af[3][1], af[3][2], af[3][3], pa + 48 * ROWB + kb);
            LDSM_X4(bf[0][0], bf[0][1], bf[0][2], bf[0][3], pb + kb);
            LDSM_X4(bf[1][0], bf[1][1], bf[1][2], bf[1][3], pb + 16 * ROWB + kb);
            LDSM_X4(bf[2][0], bf[2][1], bf[2][2], bf[2][3], pb + 32 * ROWB + kb);
            LDSM_X4(bf[3][0], bf[3][1], bf[3][2], bf[3][3], pb + 48 * ROWB + kb);
#pragma unroll
            for (int rm = 0; rm < 4; ++rm) {
#pragma unroll
                for (int cn = 0; cn < 8; ++cn) {
                    const int p = cn >> 1, s = cn & 1;
                    MMA(acc[rm][cn], af[rm][0], af[rm][1], af[rm][2], af[rm][3],
                        bf[p][s], bf[p][s + 2]);
                }
            }
        }
        if (ch + 2 < NCH) load_chunk((ch + 2) % NSTG, ch + 2);
    }

    // epilogue: sqrt-sum; mask left 128 cols when i == 2g (diagonal block)
    float lsum = 0.f;
#pragma unroll
    for (int cn = 0; cn < 8; ++cn) {
        const bool valid = !skipL || (wc + cn * 8 >= 128);
        if (valid) {
#pragma unroll
            for (int rm = 0; rm < 4; ++rm)
#pragma unroll
                for (int c2 = 0; c2 < 4; ++c2)
                    lsum += fsqrt_fast(acc[rm][cn][c2]);
        }
    }
#pragma unroll
    for (int off = 16; off > 0; off >>= 1)
        lsum += __shfl_xor_sync(0xFFFFFFFFu, lsum, off);
    if (lane == 0) wsum[wid] = lsum;
    __syncthreads();
    if (tid == 0) {
        float s = 0.f;
#pragma unroll
        for (int k = 0; k < 8; ++k) s += wsum[k];
        atomicAdd(&g_acc[1 + gram], s);
    }
}

// ---------------- kernel 3: finalize ----------------
__global__ void k_final(float* __restrict__ out) {
    // operands 256*q^2 -> G x65536 -> sqrt x256. Each unordered pair counted once
    // -> raw_g (i!=j) = 2*acc/256; cluster = -(raw_a+raw_b)/(2*scale)
    const float scale = (float)(NC * NC - NC) * sqrtf((float)BATCHB);
    const float self = -g_acc[0] / (float)(BATCHB * NC);
    const float clus = -(2.0f * (g_acc[1] + g_acc[2]) / 256.0f) / (2.0f * scale);
    out[0] = self + clus;
}

extern "C" void kernel_launch(void* const* d_in, const int* in_sizes, int n_in,
                              void* d_out, int out_size) {
    const float* emb = (const float*)d_in[0];
    float* out = (float*)d_out;
    cudaFuncSetAttribute(k_gram, cudaFuncAttributeMaxDynamicSharedMemorySize, SMEM_DYN);
    k_zero<<<1, 32>>>();
    k_softmax<<<dim3(32, 64), 512>>>(emb);
    k_gram<<<dim3(NTILES, 2), 256, SMEM_DYN>>>();
    k_final<<<1, 1>>>(out);
}

// round 15
// speedup vs baseline: 1.1457x; 1.1457x over previous
#include <cuda_runtime.h>
#include <cuda_fp16.h>
#include <cstdint>
#include <math.h>

#define NC      64
#define DHEAD   128
#define BATCHB  512
#define COLS    8192
#define NPAIRS  2016
#define KC      64              // k-halfs per chunk (128B row)
#define NCH     8
#define ROWB    144             // smem row stride bytes (64 halfs + 8 pad)
#define A_ST    (DHEAD * ROWB)  // 18432
#define STG     (2 * A_ST)      // 36864 per stage (A+B)
#define NSTG    3
#define SMEM_DYN (NSTG * STG)   // 110592 -> 2 CTAs/SM (221KB)

// fp16 of 256*q^2, transposed [gram][col][b]  (16.8 MB, L2-resident)
__device__ __half g_Xt[2ULL * COLS * BATCHB];
__device__ float  g_acc[4];

__device__ __forceinline__ float fsqrt_fast(float x) {
    float r; asm("sqrt.approx.f32 %0, %1;" : "=f"(r) : "f"(x)); return r;
}
__device__ __forceinline__ uint32_t smem_u32(const void* p) {
    uint32_t a;
    asm("{ .reg .u64 t; cvta.to.shared.u64 t, %1; cvt.u32.u64 %0, t; }" : "=r"(a) : "l"(p));
    return a;
}
#define CP16(dst, src) \
    asm volatile("cp.async.cg.shared.global [%0], [%1], 16;" :: "r"(dst), "l"(src))
#define CP_COMMIT() asm volatile("cp.async.commit_group;" ::: "memory")
#define CP_WAIT1()  asm volatile("cp.async.wait_group 1;"  ::: "memory")
#define CP_WAIT0()  asm volatile("cp.async.wait_group 0;"  ::: "memory")
#define LDSM_X4(r0, r1, r2, r3, a) \
    asm volatile("ldmatrix.sync.aligned.m8n8.x4.shared.b16 {%0,%1,%2,%3}, [%4];" \
                 : "=r"(r0), "=r"(r1), "=r"(r2), "=r"(r3) : "r"(a))
#define MMA(d, a0, a1, a2, a3, b0, b1) \
    asm volatile( \
        "mma.sync.aligned.m16n8k16.row.col.f32.f16.f16.f32 " \
        "{%0,%1,%2,%3}, {%4,%5,%6,%7}, {%8,%9}, {%0,%1,%2,%3};" \
        : "+f"((d)[0]), "+f"((d)[1]), "+f"((d)[2]), "+f"((d)[3]) \
        : "r"(a0), "r"(a1), "r"(a2), "r"(a3), "r"(b0), "r"(b1))

// ---------------- kernel 0 ----------------
__global__ void k_zero() { if (threadIdx.x < 4) g_acc[threadIdx.x] = 0.0f; }

// ---------------- kernel 1: softmax -> fp16 256*q^2 transposed + self-sim dot ----------------
__global__ void k_softmax(const float* __restrict__ emb) {
    const int c    = blockIdx.y;
    const int b0   = blockIdx.x * 16;
    const int w    = threadIdx.x >> 5;
    const int lane = threadIdx.x & 31;

    __shared__ __align__(16) __half sm_t[2][DHEAD][16];
    __shared__ float dotred[16];

    const int b = b0 + w;
    const float* pa = emb + (size_t)b * COLS + c * DHEAD;
    const float* pb = emb + (size_t)(b + BATCHB) * COLS + c * DHEAD;

    float xa[4], xb[4];
#pragma unroll
    for (int p = 0; p < 4; ++p) { xa[p] = pa[lane + 32 * p]; xb[p] = pb[lane + 32 * p]; }

    float ma = fmaxf(fmaxf(xa[0], xa[1]), fmaxf(xa[2], xa[3]));
    float mb = fmaxf(fmaxf(xb[0], xb[1]), fmaxf(xb[2], xb[3]));
#pragma unroll
    for (int off = 16; off > 0; off >>= 1) {
        ma = fmaxf(ma, __shfl_xor_sync(0xFFFFFFFFu, ma, off));
        mb = fmaxf(mb, __shfl_xor_sync(0xFFFFFFFFu, mb, off));
    }
    float ea[4], eb[4], sa = 0.f, sb = 0.f;
#pragma unroll
    for (int p = 0; p < 4; ++p) {
        ea[p] = __expf(xa[p] - ma); sa += ea[p];
        eb[p] = __expf(xb[p] - mb); sb += eb[p];
    }
#pragma unroll
    for (int off = 16; off > 0; off >>= 1) {
        sa += __shfl_xor_sync(0xFFFFFFFFu, sa, off);
        sb += __shfl_xor_sync(0xFFFFFFFFu, sb, off);
    }
    const float ia = 16.0f / sa, ib = 16.0f / sb;
    float dot = 0.f;
#pragma unroll
    for (int p = 0; p < 4; ++p) {
        float qa = ea[p] * ia;                       // 16*q_a
        float qb = eb[p] * ib;
        dot += qa * qb;                              // 256*qa*qb
        sm_t[0][lane + 32 * p][w] = __float2half_rn(qa * qa);   // 256*q^2
        sm_t[1][lane + 32 * p][w] = __float2half_rn(qb * qb);
    }
#pragma unroll
    for (int off = 16; off > 0; off >>= 1)
        dot += __shfl_xor_sync(0xFFFFFFFFu, dot, off);
    if (lane == 0) dotred[w] = dot;
    __syncthreads();
    if (threadIdx.x == 0) {
        float s = 0.f;
#pragma unroll
        for (int k = 0; k < 16; ++k) s += dotred[k];
        atomicAdd(&g_acc[0], s * (1.0f / 256.0f));
    }
    const int tid = threadIdx.x;
    const int g = tid >> 8;
    const int d = (tid >> 1) & 127;
    const int h = tid & 1;
    uint4 v = *(const uint4*)&sm_t[g][d][h * 8];
    __half* dst = g_Xt + (size_t)g * COLS * BATCHB
                + (size_t)(c * DHEAD + d) * BATCHB + (b0 + h * 8);
    *(uint4*)dst = v;
}

// ---------------- kernel 2: 128x128 Gram tile, 16 warps of 32x32, 2 CTAs/SM ----------------
// grid (2016, 2): pair x gram. 512 threads: warp grid 4(row) x 4(col).
__global__ void __launch_bounds__(512, 2) k_gram() {
    extern __shared__ __align__(16) char dsm[];
    __shared__ float wsum[16];

    const uint32_t sbase = smem_u32(dsm);
    const int tid  = threadIdx.x;
    const int wid  = tid >> 5;
    const int lane = tid & 31;

    // pair decode: t = j*(j-1)/2 + i, i < j
    const int t = blockIdx.x;
    int j = (int)((1.0f + sqrtf(8.0f * (float)t + 1.0f)) * 0.5f);
    while (j * (j - 1) / 2 > t) --j;
    while ((j + 1) * j / 2 <= t) ++j;
    const int i = t - j * (j - 1) / 2;
    const int gram = blockIdx.y;

    const __half* xg = g_Xt + (size_t)gram * COLS * BATCHB;
    const __half* gA = xg + (size_t)j * DHEAD * BATCHB;
    const __half* gB = xg + (size_t)i * DHEAD * BATCHB;

    const int wr = (wid & 3) * 32;     // warp row base
    const int wc = (wid >> 2) * 32;    // warp col base

    const int lrow = lane & 15;
    const uint32_t lkb = (uint32_t)(lane >> 4) * 16;
    const uint32_t aoff_l = (uint32_t)(wr + lrow) * ROWB + lkb;
    const uint32_t boff_l = A_ST + (uint32_t)(wc + lrow) * ROWB + lkb;

    float acc[2][4][4];
#pragma unroll
    for (int a = 0; a < 2; ++a)
#pragma unroll
        for (int b = 0; b < 4; ++b)
#pragma unroll
            for (int c2 = 0; c2 < 4; ++c2) acc[a][b][c2] = 0.f;

    // chunk: 128 rows x 8 x 16B per operand = 2048 CP16 over 512 threads (4/thread)
    auto load_chunk = [&](int st, int ch) {
        const uint32_t ao = sbase + st * STG;
        const uint32_t bo = ao + A_ST;
#pragma unroll
        for (int it = 0; it < 2; ++it) {
            const int u = tid + it * 512;           // 0..1023
            const int r = u >> 3, seg = u & 7;
            const size_t goff = (size_t)r * BATCHB + ch * KC + seg * 8;
            CP16(ao + r * ROWB + seg * 16, gA + goff);
            CP16(bo + r * ROWB + seg * 16, gB + goff);
        }
        CP_COMMIT();
    };

    load_chunk(0, 0);
    load_chunk(1, 1);

#pragma unroll 1
    for (int ch = 0; ch < NCH; ++ch) {
        if (ch + 1 < NCH) CP_WAIT1(); else CP_WAIT0();
        __syncthreads();

        const uint32_t sst = sbase + (ch % NSTG) * STG;
        const uint32_t pa = sst + aoff_l;
        const uint32_t pb = sst + boff_l;

#pragma unroll
        for (int ks = 0; ks < 4; ++ks) {
            const uint32_t kb = (uint32_t)ks * 32;
            uint32_t a0[4], a1[4], bf[2][4];
            LDSM_X4(a0[0], a0[1], a0[2], a0[3], pa + kb);               // rows wr..wr+15
            LDSM_X4(a1[0], a1[1], a1[2], a1[3], pa + 16 * ROWB + kb);   // rows wr+16..31
            LDSM_X4(bf[0][0], bf[0][1], bf[0][2], bf[0][3], pb + kb);             // cols wc..+15
            LDSM_X4(bf[1][0], bf[1][1], bf[1][2], bf[1][3], pb + 16 * ROWB + kb); // cols wc+16..+31
#pragma unroll
            for (int p = 0; p < 2; ++p) {
#pragma unroll
                for (int s = 0; s < 2; ++s) {
                    const int cn = 2 * p + s;
                    MMA(acc[0][cn], a0[0], a0[1], a0[2], a0[3], bf[p][s], bf[p][s + 2]);
                    MMA(acc[1][cn], a1[0], a1[1], a1[2], a1[3], bf[p][s], bf[p][s + 2]);
                }
            }
        }
        if (ch + 2 < NCH) load_chunk((ch + 2) % NSTG, ch + 2);
    }

    // epilogue: sum sqrt over all accumulator entries
    float lsum = 0.f;
#pragma unroll
    for (int a = 0; a < 2; ++a)
#pragma unroll
        for (int b = 0; b < 4; ++b)
#pragma unroll
            for (int c2 = 0; c2 < 4; ++c2) lsum += fsqrt_fast(acc[a][b][c2]);
#pragma unroll
    for (int off = 16; off > 0; off >>= 1)
        lsum += __shfl_xor_sync(0xFFFFFFFFu, lsum, off);
    if (lane == 0) wsum[wid] = lsum;
    __syncthreads();
    if (tid == 0) {
        float s = 0.f;
#pragma unroll
        for (int k = 0; k < 16; ++k) s += wsum[k];
        atomicAdd(&g_acc[1 + gram], s);
    }
}

// ---------------- kernel 3: finalize ----------------
__global__ void k_final(float* __restrict__ out) {
    // operands 256*q^2 -> G x65536 -> sqrt x256. raw_g (i!=j) = 2*acc/256.
    const float scale = (float)(NC * NC - NC) * sqrtf((float)BATCHB);
    const float self = -g_acc[0] / (float)(BATCHB * NC);
    const float clus = -(2.0f * (g_acc[1] + g_acc[2]) / 256.0f) / (2.0f * scale);
    out[0] = self + clus;
}

extern "C" void kernel_launch(void* const* d_in, const int* in_sizes, int n_in,
                              void* d_out, int out_size) {
    const float* emb = (const float*)d_in[0];
    float* out = (float*)d_out;
    cudaFuncSetAttribute(k_gram, cudaFuncAttributeMaxDynamicSharedMemorySize, SMEM_DYN);
    k_zero<<<1, 32>>>();
    k_softmax<<<dim3(32, 64), 512>>>(emb);
    k_gram<<<dim3(NPAIRS, 2), 512, SMEM_DYN>>>();
    k_final<<<1, 1>>>(out);
}